// round 8
// baseline (speedup 1.0000x reference)
#include <cuda_runtime.h>
#include <cuda_bf16.h>
#include <math.h>

// Problem shape (fixed by dataset): T=512, N=512, C=80, S=128, L=257
#define TT 512
#define CC 80
#define SS 128
#define NEGV  (-1e30f)
#define LOG2E 1.4426950408889634f
#define LN2   0.6931471805599453f
#define NT    128                // 4 warps; thread tid owns cells 2tid+1, 2tid+2

__device__ __forceinline__ float ex2f(float x) {
    float r; asm("ex2.approx.ftz.f32 %0, %1;" : "=f"(r) : "f"(x)); return r;
}
__device__ __forceinline__ float lg2f(float x) {
    float r; asm("lg2.approx.f32 %0, %1;" : "=f"(r) : "f"(x)); return r;
}
// 3-term log2-sum-exp2 with input sort: 2 ex2 + 1 lg2
__device__ __forceinline__ float lse3(float x, float y, float z) {
    float hi  = fmaxf(x, y), lo1 = fminf(x, y);
    float m   = fmaxf(hi, z);
    float mid = fmaxf(lo1, fminf(hi, z));
    float lo  = fminf(lo1, z);
    return m + lg2f(1.0f + ex2f(mid - m) + ex2f(lo - m));
}
// 2-term: 1 ex2 + 1 lg2
__device__ __forceinline__ float lse2(float x, float y) {
    float m = fmaxf(x, y), lo = fminf(x, y);
    return m + lg2f(1.0f + ex2f(lo - m));
}

// One block (128 threads, 4 warps) per sequence; lattice in registers
// (a0 = cell 2tid+1, a1 = cell 2tid+2; alpha0 = cell 0). NO per-step
// __syncthreads: warp w consumes warp w-1's boundary (its lane-31 a0/a1 of
// step t-1) through a 512-deep smem buffer, guarded by a release/acquire
// progress counter. Left-to-right dataflow only -> no deadlock, ~1-step skew.
__global__ __launch_bounds__(NT)
void ctc_loss_kernel(const float* __restrict__ log_probs,     // (T, N, C)
                     const int*   __restrict__ targets,       // (N, S)
                     const int*   __restrict__ input_lengths, // (N,)
                     const int*   __restrict__ target_lengths,// (N,)
                     float*       __restrict__ out,           // (N,)
                     int N)
{
    __shared__ float2 bnd[3][TT];    // [producer warp][t] = lane31 {a0, a1}
    __shared__ int    prog[3];       // highest t published by warp w
    __shared__ float  fin[260];      // epilogue gather

    const int tid  = threadIdx.x;
    const int lane = tid & 31;
    const int w    = tid >> 5;
    const int n    = blockIdx.x;
    const int len  = input_lengths[n];

    // Time-invariant: my label (cell 2tid+1) and skip permission
    const int  c    = targets[n * SS + tid];
    const bool skip = (tid > 0) && (c != targets[n * SS + tid - 1]);

    const size_t tstride = (size_t)N * CC;
    const float* lp = log_probs + (size_t)n * CC;

    // shared-window addresses for the progress counters
    const unsigned paddr_self = (unsigned)__cvta_generic_to_shared(&prog[w]);
    const unsigned paddr_left = (w > 0) ?
        (unsigned)__cvta_generic_to_shared(&prog[w - 1]) : 0u;

    // ---- t = 0 (log2 domain) ----
    float alpha0 = __ldg(lp) * LOG2E;                       // cell 0 (blank)
    float a0 = (tid == 0) ? __ldg(lp + c) * LOG2E : NEGV;   // cell 1
    float a1 = NEGV;                                        // cell 2

    if (w < 3 && lane == 31) bnd[w][0] = make_float2(a0, a1);
    if (tid < 3) prog[tid] = 0;

    // raw emissions for t = 1 (row 1 always exists: T=512)
    const float* r1 = lp + tstride;
    float pc = __ldg(r1 + c);     // my label emission
    float pb = __ldg(r1);         // blank emission
    __syncthreads();              // publish t=0 state + prog init

    // ---- DP loop: no barriers; acquire/release dataflow between warps ----
    for (int t = 1; t < len; ++t) {
        // prefetch raw emissions for t+1 (clamped on last iter; unused then)
        const int tn = (t + 1 < len) ? t + 1 : t;
        const float* row = lp + (size_t)tn * tstride;
        float qc = __ldg(row + c);
        float qb = __ldg(row);

        // left-boundary cells 2tid and 2tid-1
        float l1, l0;
        if (w > 0) {
            int pv;  // spin until left warp published step t-1 (uniform, no divergence)
            do {
                asm volatile("ld.acquire.cta.shared.b32 %0, [%1];"
                             : "=r"(pv) : "r"(paddr_left) : "memory");
            } while (pv < t - 1);
            float2 bb = bnd[w - 1][t - 1];
            l1 = bb.y; l0 = bb.x;
        } else {
            l1 = alpha0; l0 = NEGV;
        }
        float s1 = __shfl_up_sync(0xffffffffu, a1, 1);
        float s0 = __shfl_up_sync(0xffffffffu, a0, 1);
        if (lane > 0) { l1 = s1; l0 = s0; }

        float n0 = fmaf(pc, LOG2E, lse3(a0, l1, skip ? l0 : NEGV)); // cell 2tid+1
        float n1 = fmaf(pb, LOG2E, lse2(a1, a0));                   // cell 2tid+2
        alpha0   = fmaf(pb, LOG2E, alpha0);                         // cell 0

        a0 = n0; a1 = n1;
        if (w < 3 && lane == 31) {
            bnd[w][t] = make_float2(a0, a1);
            asm volatile("st.release.cta.shared.b32 [%0], %1;"
                         :: "r"(paddr_self), "r"(t) : "memory");
        }
        pc = qc; pb = qb;
    }

    // ---- epilogue: gather lattice, tid 0 combines cells 2*tl and 2*tl-1 ----
    fin[2 * tid + 1] = a0;
    fin[2 * tid + 2] = a1;
    if (tid == 0) fin[0] = alpha0;
    __syncthreads();

    if (tid == 0) {
        const int tl = target_lengths[n];
        float v1 = fin[2 * tl];
        float v2 = fin[2 * tl - 1];
        float m  = fmaxf(v1, v2);
        float loss = -(m + lg2f(ex2f(v1 - m) + ex2f(v2 - m))) * LN2;
        if (!isfinite(loss) || loss >= 1e10f) loss = 0.0f;
        out[n] = loss;
    }
}

extern "C" void kernel_launch(void* const* d_in, const int* in_sizes, int n_in,
                              void* d_out, int out_size)
{
    const float* log_probs      = (const float*)d_in[0];
    const int*   targets        = (const int*)  d_in[1];
    const int*   input_lengths  = (const int*)  d_in[2];
    const int*   target_lengths = (const int*)  d_in[3];
    float*       out            = (float*)d_out;

    const int N = in_sizes[2];   // batch from input_lengths element count

    ctc_loss_kernel<<<N, NT>>>(log_probs, targets, input_lengths,
                               target_lengths, out, N);
}

// round 11
// speedup vs baseline: 1.3222x; 1.3222x over previous
#include <cuda_runtime.h>
#include <cuda_bf16.h>
#include <math.h>

// Problem shape (fixed by dataset): T=512, N=512, C=80, S=128, L=257
#define CC 80
#define SS 128
#define LOG2E 1.4426950408889634f
#define LN2   0.6931471805599453f
#define NT    128                // 4 warps; thread tid owns cells 2tid+1, 2tid+2

__device__ __forceinline__ float ex2f(float x) {
    float r; asm("ex2.approx.ftz.f32 %0, %1;" : "=f"(r) : "f"(x)); return r;
}
__device__ __forceinline__ float lg2f(float x) {
    float r; asm("lg2.approx.f32 %0, %1;" : "=f"(r) : "f"(x)); return r;
}
// exact 2^d for d <= 0 (flush below 2^-126); d>=-2^30 assumed
__device__ __forceinline__ float exp2i(int d) {
    int b = 127 + d; b = b < 0 ? 0 : b;
    return __int_as_float(b << 23);
}

// One block (128 threads, 4 warps) per sequence. Linear-domain CTC forward
// with PER-THREAD floating exponents: thread state is (a0, a1, e) meaning
// true alpha = a * 2^e, a kept in [0,2) by a bit-trick renorm every step.
// Zero MUFU on the recurrence chain (the 2 ex2 emission conversions depend
// only on prefetched log-probs). One __syncthreads per step, 3 shuffles.
__global__ __launch_bounds__(NT)
void ctc_loss_kernel(const float* __restrict__ log_probs,     // (T, N, C)
                     const int*   __restrict__ targets,       // (N, S)
                     const int*   __restrict__ input_lengths, // (N,)
                     const int*   __restrict__ target_lengths,// (N,)
                     float*       __restrict__ out,           // (N,)
                     int N)
{
    __shared__ float4 bnd[2][4];   // [parity][warp] = lane31 {a0, a1, e-bits, -}
    __shared__ float  finv[260];   // epilogue mantissas
    __shared__ int    fine[260];   // epilogue exponents

    const int tid  = threadIdx.x;
    const int lane = tid & 31;
    const int w    = tid >> 5;
    const int n    = blockIdx.x;
    const int len  = input_lengths[n];

    // Time-invariant: my label (cell 2tid+1) and skip mask
    const int   c     = targets[n * SS + tid];
    const float skipf = (tid > 0 && c != targets[n * SS + tid - 1]) ? 1.0f : 0.0f;

    const size_t tstride = (size_t)N * CC;
    const float* lp = log_probs + (size_t)n * CC;

    // ---- t = 0 ----
    float a0 = (tid == 0) ? ex2f(__ldg(lp + c) * LOG2E) : 0.0f;  // cell 2tid+1
    float a1 = 0.0f;                                             // cell 2tid+2
    int   e  = 0;
    float alpha0 = ex2f(__ldg(lp) * LOG2E);                      // cell 0
    int   e0 = 0;

    if (lane == 31) bnd[0][w] = make_float4(a0, a1, __int_as_float(e), 0.0f);

    // raw (log) emissions for t = 1
    float pc = __ldg(lp + tstride + c);
    float pb = __ldg(lp + tstride);
    __syncthreads();

    // ---- DP loop ----
    for (int t = 1; t < len; ++t) {
        // prefetch raw emissions for t+1 (clamped on last iter)
        const int tn = (t + 1 < len) ? t + 1 : t;
        const float* row = lp + (size_t)tn * tstride;
        float qc = __ldg(row + c);
        float qb = __ldg(row);

        // linear emission multipliers (MUFU, but off the alpha-dependency chain)
        float epc = ex2f(pc * LOG2E);
        float epb = ex2f(pb * LOG2E);

        // left neighbor state: cells 2tid, 2tid-1 and their exponent
        float l1 = __shfl_up_sync(0xffffffffu, a1, 1);
        float l0 = __shfl_up_sync(0xffffffffu, a0, 1);
        int   eL = __shfl_up_sync(0xffffffffu, e, 1);
        if (lane == 0) {
            if (w == 0) { l1 = alpha0; l0 = 0.0f; eL = e0; }
            else {
                float4 bb = bnd[(t - 1) & 1][w - 1];
                l0 = bb.x; l1 = bb.y; eL = __float_as_int(bb.z);
            }
        }

        // exponent reconciliation (exact power-of-2 scaling)
        int   m  = max(e, eL);
        float sS = exp2i(e  - m);
        float sL = exp2i(eL - m);
        float b0 = a0 * sS;
        float b1 = a1 * sS;

        float n0 = fmaf(l0 * sL, skipf, fmaf(l1, sL, b0)) * epc;  // label cell
        float n1 = (b1 + b0) * epb;                               // blank cell

        // renormalize to [0,2) with exact 2^k (pure bit ops)
        float v  = fmaxf(n0, n1);
        int   k  = (__float_as_int(v) >> 23) & 255;
        float nf = __int_as_float((254 - k) << 23);
        a0 = n0 * nf;
        a1 = n1 * nf;
        e  = m + k - 127;

        // cell 0: blank self-loop with its own exponent
        alpha0 *= epb;
        int k0 = (__float_as_int(alpha0) >> 23) & 255;
        alpha0 *= __int_as_float((254 - k0) << 23);
        e0 += k0 - 127;

        if (lane == 31) bnd[t & 1][w] = make_float4(a0, a1, __int_as_float(e), 0.0f);
        pc = qc; pb = qb;
        __syncthreads();
    }

    // ---- epilogue: combine cells 2*tl and 2*tl-1 ----
    finv[2 * tid + 1] = a0;  fine[2 * tid + 1] = e;
    finv[2 * tid + 2] = a1;  fine[2 * tid + 2] = e;
    if (tid == 0) { finv[0] = alpha0; fine[0] = e0; }
    __syncthreads();

    if (tid == 0) {
        const int tl = target_lengths[n];
        float v1 = finv[2 * tl];     int ee1 = fine[2 * tl];
        float v2 = finv[2 * tl - 1]; int ee2 = fine[2 * tl - 1];
        int   mm = max(ee1, ee2);
        float vv = v1 * exp2i(ee1 - mm) + v2 * exp2i(ee2 - mm);
        float loss = -(lg2f(vv) + (float)mm) * LN2;
        if (!isfinite(loss) || loss >= 1e10f) loss = 0.0f;
        out[n] = loss;
    }
}

extern "C" void kernel_launch(void* const* d_in, const int* in_sizes, int n_in,
                              void* d_out, int out_size)
{
    const float* log_probs      = (const float*)d_in[0];
    const int*   targets        = (const int*)  d_in[1];
    const int*   input_lengths  = (const int*)  d_in[2];
    const int*   target_lengths = (const int*)  d_in[3];
    float*       out            = (float*)d_out;

    const int N = in_sizes[2];   // batch from input_lengths element count

    ctc_loss_kernel<<<N, NT>>>(log_probs, targets, input_lengths,
                               target_lengths, out, N);
}